// round 5
// baseline (speedup 1.0000x reference)
#include <cuda_runtime.h>
#include <cstdint>

// Inverse 2D Haar DWT — R2 memory shape, persistent grid-stride (one wave).
//
// Inputs: 4 x (4,64,256,256) fp32.  Output: (4,64,512,512) fp32.
//
// R2 shape (74.3us kernel, 82% DRAM): per unit, load one float2 from each of
// the 4 bands (LDG.64, warp = 256B contiguous per band) and store two float4s
// (STG.128, warp = 512B contiguous per output row). All full 128B sectors,
// streaming (.cs) hints.
//
// Change vs R2: persistent kernel with grid sized to exactly fill the chip
// (one wave), grid-stride loop over units. Removes ~27 wave transitions and
// the fractional tail wave; loop structure lets ptxas overlap next-iteration
// loads with current stores.

static constexpr int W2_IN  = 256 / 2;             // 128 float2 per input row
static constexpr int H_IN   = 256;
static constexpr int W4_OUT = 512 / 4;             // 128 float4 per output row
static constexpr int PLANE_OUT_F4 = 512 * 512 / 4; // 65536

__global__ __launch_bounds__(256)
void haar_idwt2_kernel(const float2* __restrict__ ll,
                       const float2* __restrict__ lh,
                       const float2* __restrict__ hl,
                       const float2* __restrict__ hh,
                       float4* __restrict__ out,
                       int n_f2)   // total float2 units = 8,388,608
{
    int stride = gridDim.x * blockDim.x;

    #pragma unroll 2
    for (int f = blockIdx.x * blockDim.x + threadIdx.x; f < n_f2; f += stride) {
        float2 vll = __ldcs(&ll[f]);
        float2 vlh = __ldcs(&lh[f]);
        float2 vhl = __ldcs(&hl[f]);
        float2 vhh = __ldcs(&hh[f]);

        int col2  = f & (W2_IN - 1);   // f % 128
        int r     = f >> 7;
        int h     = r & (H_IN - 1);    // r % 256
        int plane = r >> 8;

        float a0 = (vll.x + vlh.x + vhl.x + vhh.x) * 0.5f;
        float b0 = (vll.x + vlh.x - vhl.x - vhh.x) * 0.5f;
        float c0 = (vll.x - vlh.x + vhl.x - vhh.x) * 0.5f;
        float d0 = (vll.x - vlh.x - vhl.x + vhh.x) * 0.5f;

        float a1 = (vll.y + vlh.y + vhl.y + vhh.y) * 0.5f;
        float b1 = (vll.y + vlh.y - vhl.y - vhh.y) * 0.5f;
        float c1 = (vll.y - vlh.y + vhl.y - vhh.y) * 0.5f;
        float d1 = (vll.y - vlh.y - vhl.y + vhh.y) * 0.5f;

        int idx0 = plane * PLANE_OUT_F4 + (2 * h) * W4_OUT + col2;  // even row
        int idx1 = idx0 + W4_OUT;                                   // odd row

        __stcs(&out[idx0], make_float4(a0, b0, a1, b1));
        __stcs(&out[idx1], make_float4(c0, d0, c1, d1));
    }
}

extern "C" void kernel_launch(void* const* d_in, const int* in_sizes, int n_in,
                              void* d_out, int out_size)
{
    const float2* ll = (const float2*)d_in[0];
    const float2* lh = (const float2*)d_in[1];
    const float2* hl = (const float2*)d_in[2];
    const float2* hh = (const float2*)d_in[3];
    float4* out = (float4*)d_out;

    int n_f2 = in_sizes[0] / 2;   // 8,388,608

    // One full wave: GB300 has 152 SMs; 8 blocks of 256 threads per SM.
    int blocks = 152 * 8;         // 1216
    int threads = 256;

    haar_idwt2_kernel<<<blocks, threads>>>(ll, lh, hl, hh, out, n_f2);
}

// round 6
// speedup vs baseline: 1.0638x; 1.0638x over previous
#include <cuda_runtime.h>
#include <cstdint>

// Inverse 2D Haar DWT, output-centric decomposition (final: R2 configuration).
//
// Inputs: 4 x (4,64,256,256) fp32.  Output: (4,64,512,512) fp32.
//
// One thread handles one float2 (2 consecutive cols j, j+1) from each band
// and writes two float4s:
//   even output row 2h : {a_j, b_j, a_{j+1}, b_{j+1}}
//   odd  output row 2h+1: {c_j, d_j, c_{j+1}, d_{j+1}}
//
// Warp-wide, loads are 32 x 8B contiguous (2 full 128B sectors / LDG.64) and
// stores are 32 x 16B contiguous (4 full sectors / STG.128) -> zero
// partial-sector wavefronts. Streaming hints (.cs) since there is zero reuse.
//
// Explored and rejected (all regressed or neutral on GB300):
//   - v8.f32 256-bit stores, fewer threads   (R3: DRAM 80.2%)
//   - 2 units/thread doubled MLP             (R4: DRAM 81.0%)
//   - persistent grid-stride single wave     (R5: regs 40, occ 63%, DRAM 74.5%)
// Binding constraint: HBM read/write turnaround on the 50/50 mixed stream;
// ~82% DRAM-active is the practical ceiling for this traffic shape.

static constexpr int W2_IN  = 256 / 2;        // 128 float2 per input row
static constexpr int H_IN   = 256;
static constexpr int W4_OUT = 512 / 4;        // 128 float4 per output row
static constexpr int PLANE_OUT_F4 = 512 * 512 / 4;  // 65536

__global__ __launch_bounds__(256)
void haar_idwt2_kernel(const float2* __restrict__ ll,
                       const float2* __restrict__ lh,
                       const float2* __restrict__ hl,
                       const float2* __restrict__ hh,
                       float4* __restrict__ out,
                       int n_f2)  // total float2 count = 4*64*256*128
{
    int f = blockIdx.x * blockDim.x + threadIdx.x;
    if (f >= n_f2) return;

    // Index math first: store addresses ready before loads complete.
    int col2  = f & (W2_IN - 1);     // f % 128
    int r     = f >> 7;
    int h     = r & (H_IN - 1);      // r % 256
    int plane = r >> 8;
    int idx0 = plane * PLANE_OUT_F4 + (2 * h) * W4_OUT + col2;  // even row
    int idx1 = idx0 + W4_OUT;                                   // odd row

    float2 vll = __ldcs(&ll[f]);
    float2 vlh = __ldcs(&lh[f]);
    float2 vhl = __ldcs(&hl[f]);
    float2 vhh = __ldcs(&hh[f]);

    float a0 = (vll.x + vlh.x + vhl.x + vhh.x) * 0.5f;
    float b0 = (vll.x + vlh.x - vhl.x - vhh.x) * 0.5f;
    float c0 = (vll.x - vlh.x + vhl.x - vhh.x) * 0.5f;
    float d0 = (vll.x - vlh.x - vhl.x + vhh.x) * 0.5f;

    float a1 = (vll.y + vlh.y + vhl.y + vhh.y) * 0.5f;
    float b1 = (vll.y + vlh.y - vhl.y - vhh.y) * 0.5f;
    float c1 = (vll.y - vlh.y + vhl.y - vhh.y) * 0.5f;
    float d1 = (vll.y - vlh.y - vhl.y + vhh.y) * 0.5f;

    __stcs(&out[idx0], make_float4(a0, b0, a1, b1));
    __stcs(&out[idx1], make_float4(c0, d0, c1, d1));
}

extern "C" void kernel_launch(void* const* d_in, const int* in_sizes, int n_in,
                              void* d_out, int out_size)
{
    const float2* ll = (const float2*)d_in[0];
    const float2* lh = (const float2*)d_in[1];
    const float2* hl = (const float2*)d_in[2];
    const float2* hh = (const float2*)d_in[3];
    float4* out = (float4*)d_out;

    int n_f2 = in_sizes[0] / 2;       // 8,388,608
    int threads = 256;
    int blocks = (n_f2 + threads - 1) / threads;

    haar_idwt2_kernel<<<blocks, threads>>>(ll, lh, hl, hh, out, n_f2);
}

// round 7
// speedup vs baseline: 1.0760x; 1.0115x over previous
#include <cuda_runtime.h>
#include <cstdint>

// Inverse 2D Haar DWT, output-centric decomposition (R2 shape, 128-thr blocks).
//
// Inputs: 4 x (4,64,256,256) fp32.  Output: (4,64,512,512) fp32.
//
// One thread handles one float2 (2 consecutive cols j, j+1) from each band
// and writes two float4s:
//   even output row 2h : {a_j, b_j, a_{j+1}, b_{j+1}}
//   odd  output row 2h+1: {c_j, d_j, c_{j+1}, d_{j+1}}
//
// Warp-wide, loads are 32 x 8B contiguous (2 full 128B sectors / LDG.64) and
// stores are 32 x 16B contiguous (4 full sectors / STG.128) -> zero
// partial-sector wavefronts. Streaming hints (.cs), zero reuse.
//
// Only change vs the proven 74.6us/81.7%DRAM config: block 256 -> 128.
// 16 blocks/SM instead of 8: finer-grained CTA replacement as blocks retire
// (less per-SM drain bubble; achieved occ was 80% < theoretical 100%), and
// the per-CTA front-batched LDG burst mass halves, smoothing L1tex queueing.
//
// Explored and rejected on GB300:
//   - v8.f32 256-bit stores, fewer threads   (R3: DRAM 80.2%)
//   - 2 units/thread doubled MLP             (R4: DRAM 81.0%)
//   - persistent grid-stride single wave     (R5: regs 40, occ 63%, DRAM 74.5%)
// Binding constraint: HBM read/write turnaround on the 50/50 mixed stream;
// ~82% DRAM-active is the practical ceiling for this traffic shape.

static constexpr int W2_IN  = 256 / 2;        // 128 float2 per input row
static constexpr int H_IN   = 256;
static constexpr int W4_OUT = 512 / 4;        // 128 float4 per output row
static constexpr int PLANE_OUT_F4 = 512 * 512 / 4;  // 65536

__global__ __launch_bounds__(128)
void haar_idwt2_kernel(const float2* __restrict__ ll,
                       const float2* __restrict__ lh,
                       const float2* __restrict__ hl,
                       const float2* __restrict__ hh,
                       float4* __restrict__ out,
                       int n_f2)  // total float2 count = 4*64*256*128
{
    int f = blockIdx.x * blockDim.x + threadIdx.x;
    if (f >= n_f2) return;

    // Index math first: store addresses ready before loads complete.
    int col2  = f & (W2_IN - 1);     // f % 128
    int r     = f >> 7;
    int h     = r & (H_IN - 1);      // r % 256
    int plane = r >> 8;
    int idx0 = plane * PLANE_OUT_F4 + (2 * h) * W4_OUT + col2;  // even row
    int idx1 = idx0 + W4_OUT;                                   // odd row

    float2 vll = __ldcs(&ll[f]);
    float2 vlh = __ldcs(&lh[f]);
    float2 vhl = __ldcs(&hl[f]);
    float2 vhh = __ldcs(&hh[f]);

    float a0 = (vll.x + vlh.x + vhl.x + vhh.x) * 0.5f;
    float b0 = (vll.x + vlh.x - vhl.x - vhh.x) * 0.5f;
    float c0 = (vll.x - vlh.x + vhl.x - vhh.x) * 0.5f;
    float d0 = (vll.x - vlh.x - vhl.x + vhh.x) * 0.5f;

    float a1 = (vll.y + vlh.y + vhl.y + vhh.y) * 0.5f;
    float b1 = (vll.y + vlh.y - vhl.y - vhh.y) * 0.5f;
    float c1 = (vll.y - vlh.y + vhl.y - vhh.y) * 0.5f;
    float d1 = (vll.y - vlh.y - vhl.y + vhh.y) * 0.5f;

    __stcs(&out[idx0], make_float4(a0, b0, a1, b1));
    __stcs(&out[idx1], make_float4(c0, d0, c1, d1));
}

extern "C" void kernel_launch(void* const* d_in, const int* in_sizes, int n_in,
                              void* d_out, int out_size)
{
    const float2* ll = (const float2*)d_in[0];
    const float2* lh = (const float2*)d_in[1];
    const float2* hl = (const float2*)d_in[2];
    const float2* hh = (const float2*)d_in[3];
    float4* out = (float4*)d_out;

    int n_f2 = in_sizes[0] / 2;       // 8,388,608
    int threads = 128;
    int blocks = (n_f2 + threads - 1) / threads;

    haar_idwt2_kernel<<<blocks, threads>>>(ll, lh, hl, hh, out, n_f2);
}